// round 1
// baseline (speedup 1.0000x reference)
#include <cuda_runtime.h>

// Problem constants
#define S_LEN 2048
#define EMB   1024
#define HEADS 16
#define DH    64
#define BATCH 2

// Scratch (no allocations allowed): qkv = [B,S,3E], ctx = [B,S,E]
__device__ float g_qkv[(size_t)BATCH * S_LEN * 3 * EMB];
__device__ float g_ctx[(size_t)BATCH * S_LEN * EMB];

// ---------------------------------------------------------------------------
// Swizzled smem indexing (float4 granularity). Row stride = 16 float4.
// phys_c4 = c4 ^ ((row>>2)&15) spreads row-strided accesses across banks.
// ---------------------------------------------------------------------------
__device__ __forceinline__ int SW(int r, int c4) {
    return r * 16 + (c4 ^ ((r >> 2) & 15));
}

__device__ __forceinline__ void fma4(float4& o, float a, const float4 v) {
    o.x += a * v.x; o.y += a * v.y; o.z += a * v.z; o.w += a * v.w;
}

// ---------------------------------------------------------------------------
// C[M,N] = A[M,K] @ B[N,K]^T + bias[N]
// 128x128 tile, K-step 8, 256 threads, 8x8 per-thread microtile.
// All dims divisible by tile sizes for this problem (M=4096, N in {3072,1024}, K=1024).
// ---------------------------------------------------------------------------
__global__ __launch_bounds__(256) void gemm_nt_bias(
    const float* __restrict__ A, const float* __restrict__ B,
    const float* __restrict__ bias, float* __restrict__ C,
    int M, int N, int K)
{
    __shared__ float As[8][128];
    __shared__ float Bs[8][128];

    const int tid = threadIdx.x;
    const int bm  = blockIdx.y * 128;
    const int bn  = blockIdx.x * 128;
    const int lr  = tid >> 1;          // 0..127 (tile row for loading)
    const int lc  = (tid & 1) * 4;     // 0 or 4 (k offset for loading)
    const int ty  = tid >> 4;          // 0..15
    const int tx  = tid & 15;          // 0..15

    float acc[8][8];
    #pragma unroll
    for (int i = 0; i < 8; i++)
        #pragma unroll
        for (int j = 0; j < 8; j++)
            acc[i][j] = 0.0f;

    const float* Ap = A + (size_t)(bm + lr) * K + lc;
    const float* Bp = B + (size_t)(bn + lr) * K + lc;

    for (int k0 = 0; k0 < K; k0 += 8) {
        float4 av = *(const float4*)(Ap + k0);
        float4 bv = *(const float4*)(Bp + k0);
        __syncthreads();
        As[lc + 0][lr] = av.x; As[lc + 1][lr] = av.y;
        As[lc + 2][lr] = av.z; As[lc + 3][lr] = av.w;
        Bs[lc + 0][lr] = bv.x; Bs[lc + 1][lr] = bv.y;
        Bs[lc + 2][lr] = bv.z; Bs[lc + 3][lr] = bv.w;
        __syncthreads();

        #pragma unroll
        for (int kk = 0; kk < 8; kk++) {
            float a[8], b[8];
            *(float4*)&a[0] = *(const float4*)&As[kk][ty * 8];
            *(float4*)&a[4] = *(const float4*)&As[kk][ty * 8 + 4];
            *(float4*)&b[0] = *(const float4*)&Bs[kk][tx * 8];
            *(float4*)&b[4] = *(const float4*)&Bs[kk][tx * 8 + 4];
            #pragma unroll
            for (int i = 0; i < 8; i++)
                #pragma unroll
                for (int j = 0; j < 8; j++)
                    acc[i][j] += a[i] * b[j];
        }
    }

    #pragma unroll
    for (int i = 0; i < 8; i++) {
        const size_t row = (size_t)(bm + ty * 8 + i);
        #pragma unroll
        for (int j4 = 0; j4 < 2; j4++) {
            const int col = bn + tx * 8 + j4 * 4;
            float4 o;
            o.x = acc[i][j4 * 4 + 0] + bias[col + 0];
            o.y = acc[i][j4 * 4 + 1] + bias[col + 1];
            o.z = acc[i][j4 * 4 + 2] + bias[col + 2];
            o.w = acc[i][j4 * 4 + 3] + bias[col + 3];
            *(float4*)&C[row * N + col] = o;
        }
    }
}

// ---------------------------------------------------------------------------
// Fused causal attention (flash-style, fp32), one block per (q-tile of 64, b*h).
// 256 threads as 16x16; each thread owns a 4(q) x 4(k) score microtile and a
// 4(q) x 4(d) output microtile. Online softmax with warp-shuffle row reduction
// (rows are distributed over the 16 tx lanes, which sit inside one half-warp).
// K smem buffer is reused to hold P after the scores are consumed (fits 48KB).
// ---------------------------------------------------------------------------
__global__ __launch_bounds__(256) void attn_kernel(
    const float* __restrict__ qkv, float* __restrict__ ctx)
{
    __shared__ float4 Qs [64 * 16];
    __shared__ float4 KPs[64 * 16];   // K tile, then reused for P
    __shared__ float4 Vs [64 * 16];

    const int qt  = blockIdx.x;       // 0..31 query tile
    const int bh  = blockIdx.y;       // 0..31
    const int b   = bh >> 4;
    const int h   = bh & 15;
    const int tid = threadIdx.x;
    const int ty  = tid >> 4;         // 0..15 -> q rows 4ty..4ty+3
    const int tx  = tid & 15;         // 0..15 -> k cols / d cols 4tx..4tx+3

    const float* base = qkv + (size_t)b * S_LEN * (3 * EMB);
    const int qoff = h * DH;
    const int koff = EMB + h * DH;
    const int voff = 2 * EMB + h * DH;

    // Load Q tile (64 rows x 64 dims) as float4, swizzled.
    #pragma unroll
    for (int i = 0; i < 4; i++) {
        const int idx = tid + 256 * i;
        const int r = idx >> 4, c4 = idx & 15;
        Qs[SW(r, c4)] = *(const float4*)(base + (size_t)(qt * 64 + r) * (3 * EMB) + qoff + c4 * 4);
    }

    const float scale = 0.125f;  // 64^-0.5
    float  m[4], l[4];
    float4 oacc[4];
    #pragma unroll
    for (int r = 0; r < 4; r++) {
        m[r] = -1e30f;
        l[r] = 0.0f;
        oacc[r] = make_float4(0.f, 0.f, 0.f, 0.f);
    }

    for (int kt = 0; kt <= qt; kt++) {
        __syncthreads();  // previous-iteration readers of KPs/Vs (and Q store at kt=0) done

        // Load K and V tiles
        #pragma unroll
        for (int i = 0; i < 4; i++) {
            const int idx = tid + 256 * i;
            const int r = idx >> 4, c4 = idx & 15;
            const float* rowp = base + (size_t)(kt * 64 + r) * (3 * EMB);
            KPs[SW(r, c4)] = *(const float4*)(rowp + koff + c4 * 4);
            Vs [SW(r, c4)] = *(const float4*)(rowp + voff + c4 * 4);
        }
        __syncthreads();

        // S = Q K^T (this thread: q rows 4ty+r, k rows 4tx+c)
        float s[4][4];
        #pragma unroll
        for (int r = 0; r < 4; r++)
            #pragma unroll
            for (int c = 0; c < 4; c++)
                s[r][c] = 0.0f;

        #pragma unroll
        for (int k4 = 0; k4 < 16; k4++) {
            float4 q[4], kk[4];
            #pragma unroll
            for (int r = 0; r < 4; r++) q[r]  = Qs [SW(4 * ty + r, k4)];
            #pragma unroll
            for (int c = 0; c < 4; c++) kk[c] = KPs[SW(4 * tx + c, k4)];
            #pragma unroll
            for (int r = 0; r < 4; r++)
                #pragma unroll
                for (int c = 0; c < 4; c++)
                    s[r][c] += q[r].x * kk[c].x + q[r].y * kk[c].y
                             + q[r].z * kk[c].z + q[r].w * kk[c].w;
        }

        // Scale + causal mask (only the diagonal tile is partially masked)
        #pragma unroll
        for (int r = 0; r < 4; r++)
            #pragma unroll
            for (int c = 0; c < 4; c++) {
                s[r][c] *= scale;
                if (kt == qt && (4 * tx + c) > (4 * ty + r)) s[r][c] = -1e30f;
            }

        // Row max over the 16 tx lanes (xor shuffles stay within half-warp)
        float mt[4];
        #pragma unroll
        for (int r = 0; r < 4; r++) {
            mt[r] = fmaxf(fmaxf(s[r][0], s[r][1]), fmaxf(s[r][2], s[r][3]));
            #pragma unroll
            for (int o = 8; o > 0; o >>= 1)
                mt[r] = fmaxf(mt[r], __shfl_xor_sync(0xffffffffu, mt[r], o));
        }

        // Online softmax update
        float p[4][4];
        #pragma unroll
        for (int r = 0; r < 4; r++) {
            const float mnew = fmaxf(m[r], mt[r]);
            const float corr = __expf(m[r] - mnew);
            float rs = 0.0f;
            #pragma unroll
            for (int c = 0; c < 4; c++) {
                p[r][c] = __expf(s[r][c] - mnew);
                rs += p[r][c];
            }
            #pragma unroll
            for (int o = 8; o > 0; o >>= 1)
                rs += __shfl_xor_sync(0xffffffffu, rs, o);
            l[r] = l[r] * corr + rs;
            m[r] = mnew;
            oacc[r].x *= corr; oacc[r].y *= corr; oacc[r].z *= corr; oacc[r].w *= corr;
        }

        __syncthreads();  // everyone done reading K from KPs
        #pragma unroll
        for (int r = 0; r < 4; r++)
            KPs[SW(4 * ty + r, tx)] = make_float4(p[r][0], p[r][1], p[r][2], p[r][3]);
        __syncthreads();

        // O += P @ V  (this thread: q rows 4ty+r, d cols 4tx..4tx+3)
        #pragma unroll
        for (int k4 = 0; k4 < 16; k4++) {
            float4 pv[4];
            #pragma unroll
            for (int r = 0; r < 4; r++) pv[r] = KPs[SW(4 * ty + r, k4)];
            const float4 v0 = Vs[SW(4 * k4 + 0, tx)];
            const float4 v1 = Vs[SW(4 * k4 + 1, tx)];
            const float4 v2 = Vs[SW(4 * k4 + 2, tx)];
            const float4 v3 = Vs[SW(4 * k4 + 3, tx)];
            #pragma unroll
            for (int r = 0; r < 4; r++) {
                fma4(oacc[r], pv[r].x, v0);
                fma4(oacc[r], pv[r].y, v1);
                fma4(oacc[r], pv[r].z, v2);
                fma4(oacc[r], pv[r].w, v3);
            }
        }
    }

    // Normalize and write ctx[b, q, h*64 + 4tx .. +3]
    #pragma unroll
    for (int r = 0; r < 4; r++) {
        const float inv = 1.0f / l[r];
        float4 o = oacc[r];
        o.x *= inv; o.y *= inv; o.z *= inv; o.w *= inv;
        const size_t row = (size_t)b * S_LEN + qt * 64 + 4 * ty + r;
        *(float4*)&ctx[row * EMB + h * DH + 4 * tx] = o;
    }
}

// ---------------------------------------------------------------------------
// Launch: qkv-proj GEMM -> fused attention -> out-proj GEMM
// ---------------------------------------------------------------------------
extern "C" void kernel_launch(void* const* d_in, const int* in_sizes, int n_in,
                              void* d_out, int out_size)
{
    const float* x     = (const float*)d_in[0];
    const float* w_in  = (const float*)d_in[1];
    const float* b_in  = (const float*)d_in[2];
    const float* w_out = (const float*)d_in[3];
    const float* b_out = (const float*)d_in[4];
    float* out = (float*)d_out;

    float *qkv = nullptr, *ctx = nullptr;
    cudaGetSymbolAddress((void**)&qkv, g_qkv);
    cudaGetSymbolAddress((void**)&ctx, g_ctx);

    const int M = BATCH * S_LEN;   // 4096

    // 1) qkv = x @ in_proj_w^T + in_proj_b   [4096, 3072]
    gemm_nt_bias<<<dim3((3 * EMB) / 128, M / 128), 256>>>(
        x, w_in, b_in, qkv, M, 3 * EMB, EMB);

    // 2) fused causal attention -> ctx [4096, 1024]
    attn_kernel<<<dim3(S_LEN / 64, BATCH * HEADS), 256>>>(qkv, ctx);

    // 3) out = ctx @ out_proj_w^T + out_proj_b   [4096, 1024]
    gemm_nt_bias<<<dim3(EMB / 128, M / 128), 256>>>(
        ctx, w_out, b_out, out, M, EMB, EMB);
}